// round 6
// baseline (speedup 1.0000x reference)
#include <cuda_runtime.h>
#include <math.h>

#define NN 100000
#define EE 1600000
#define SWO 132   // float stride for Ws rows (o-dim), 16B-aligned
#define SAD 131   // float2 stride for As2 rows (n-dim), odd for conflict-light staging

// ---- scratch (device globals; no allocation allowed) ----
__device__ int   g_deg[NN];
__device__ int   g_row_start[NN];
__device__ int   g_pos[EE];
__device__ int   g_csr_src[EE];
__device__ float g_agg1[NN * 64];
__device__ float g_p[NN * 64];
__device__ float g_r[NN * 64];

typedef unsigned long long u64;

__device__ __forceinline__ u64 ffma2(u64 a, u64 b, u64 c) {
    u64 d;
    asm("fma.rn.f32x2 %0, %1, %2, %3;" : "=l"(d) : "l"(a), "l"(b), "l"(c));
    return d;
}
__device__ __forceinline__ void upk2(u64 v, float& lo, float& hi) {
    asm("mov.b64 {%0,%1}, %2;" : "=f"(lo), "=f"(hi) : "l"(v));
}

// ---------------- CSR build ----------------

__global__ void k_count(const int* __restrict__ dst) {
    int e = blockIdx.x * blockDim.x + threadIdx.x;
    if (e < EE) {
        int pos = atomicAdd(&g_deg[dst[e]], 1);
        g_pos[e] = pos;
    }
}

__global__ void k_scan() {
    __shared__ int ssum[1024];
    int tid = threadIdx.x;
    const int per = (NN + 1023) / 1024;
    int begin = tid * per;
    int end = begin + per; if (end > NN) end = NN;
    int s = 0;
    for (int i = begin; i < end; i++) s += g_deg[i];
    ssum[tid] = s;
    __syncthreads();
    for (int off = 1; off < 1024; off <<= 1) {
        int v = 0;
        if (tid >= off) v = ssum[tid - off];
        __syncthreads();
        ssum[tid] += v;
        __syncthreads();
    }
    int run = ssum[tid] - s;
    for (int i = begin; i < end; i++) { g_row_start[i] = run; run += g_deg[i]; }
}

__global__ void k_fill(const int* __restrict__ src, const int* __restrict__ dst) {
    int e = blockIdx.x * blockDim.x + threadIdx.x;
    if (e < EE) {
        int d = dst[e];
        g_csr_src[g_row_start[d] + g_pos[e]] = src[e];
    }
}

// ---------------- layer-1 aggregation (half-warp per node, proven) ----------

__global__ void k_agg64(const float* __restrict__ feat) {
    int hw = (blockIdx.x * blockDim.x + threadIdx.x) >> 4;
    int lane = threadIdx.x & 15;
    if (hw >= NN) return;
    int start = g_row_start[hw];
    int d = g_deg[hw];
    const int* cs = g_csr_src + start;
    float4 a[8];
#pragma unroll
    for (int k = 0; k < 8; k++) a[k] = make_float4(0.f, 0.f, 0.f, 0.f);
    int j = 0;
    for (; j + 8 <= d; j += 8) {
        int s[8];
#pragma unroll
        for (int k = 0; k < 8; k++) s[k] = cs[j + k];
#pragma unroll
        for (int k = 0; k < 8; k++) {
            float4 v = ((const float4*)(feat + (size_t)s[k] * 64))[lane];
            a[k].x += v.x; a[k].y += v.y; a[k].z += v.z; a[k].w += v.w;
        }
    }
    for (; j < d; j++) {
        float4 v = ((const float4*)(feat + (size_t)cs[j] * 64))[lane];
        a[0].x += v.x; a[0].y += v.y; a[0].z += v.z; a[0].w += v.w;
    }
    float4 s0, s1;
    s0.x = (a[0].x + a[1].x) + (a[2].x + a[3].x);
    s0.y = (a[0].y + a[1].y) + (a[2].y + a[3].y);
    s0.z = (a[0].z + a[1].z) + (a[2].z + a[3].z);
    s0.w = (a[0].w + a[1].w) + (a[2].w + a[3].w);
    s1.x = (a[4].x + a[5].x) + (a[6].x + a[7].x);
    s1.y = (a[4].y + a[5].y) + (a[6].y + a[7].y);
    s1.z = (a[4].z + a[5].z) + (a[6].z + a[7].z);
    s1.w = (a[4].w + a[5].w) + (a[6].w + a[7].w);
    float inv = 1.0f / (float)(d > 0 ? d : 1);
    float4 r;
    r.x = (s0.x + s1.x) * inv;
    r.y = (s0.y + s1.y) * inv;
    r.z = (s0.z + s1.z) * inv;
    r.w = (s0.w + s1.w) * inv;
    ((float4*)(g_agg1 + (size_t)hw * 64))[lane] = r;
}

// ---------------- fused transform: both layer GEMMs --------------------------
// New operand mapping:
//  - warp w owns outputs 16w..16w+15 as 8 f32x2 OUT-pairs (W loads are
//    lane-uniform -> broadcast LDS, natural layout, no duplication)
//  - lane l owns nodes {l, l+32, l+64, l+96}; A stored duplicated {a,a}
//    (conflict-free LDS.64 across lanes)
// Crossbar per warp-kstep: 4 A-LDS + 8 W-broadcast-LDS vs 32 FFMA2.

__global__ __launch_bounds__(256, 1)
void k_xform(const float* __restrict__ x,
             const float* __restrict__ W1l, const float* __restrict__ W1r,
             const float* __restrict__ b1,
             const float* __restrict__ W2l, const float* __restrict__ W2r) {
    extern __shared__ float sm[];
    float*  Ws  = sm;                          // [128 c][SWO] float (natural)
    float2* As2 = (float2*)(Ws + 128 * SWO);   // [128 c][SAD] float2 {a,a}
    float*  bs  = (float*)(As2 + 128 * SAD);   // [128]
    int tid = threadIdx.x;
    int n0 = blockIdx.x * 128;

    // stage W1 natural, c-major: c<64 -> W1l, c>=64 -> W1r
    for (int idx = tid; idx < 128 * 64; idx += 256) {
        int o = idx >> 6, c = idx & 63;
        Ws[c * SWO + o]        = W1l[idx];
        Ws[(c + 64) * SWO + o] = W1r[idx];
    }
    if (tid < 128) bs[tid] = b1[tid];
    // stage A duplicated: As2[c][n] = {v,v}; c<64 agg1, c>=64 x
    for (int idx = tid; idx < 128 * 64; idx += 256) {
        int n = idx >> 6, c = idx & 63;
        int nn = n0 + n; if (nn >= NN) nn = NN - 1;
        float va = g_agg1[(size_t)nn * 64 + c];
        float vx = x[(size_t)nn * 64 + c];
        As2[c * SAD + n]        = make_float2(va, va);
        As2[(c + 64) * SAD + n] = make_float2(vx, vx);
    }
    __syncthreads();

    int w  = tid >> 5;   // warp id: outs 16w..16w+15
    int ln = tid & 31;   // lane: nodes ln+32m

    u64 acc[8][4];       // acc[k][m]: out-pair (16w+2k, 16w+2k+1), node ln+32m
#pragma unroll
    for (int k = 0; k < 8; k++)
#pragma unroll
        for (int m = 0; m < 4; m++) acc[k][m] = 0ULL;

    // ---- GEMM1 ----
#pragma unroll 2
    for (int c = 0; c < 128; c++) {
        u64 aa[4];
#pragma unroll
        for (int m = 0; m < 4; m++)
            aa[m] = *(const u64*)(As2 + c * SAD + ln + 32 * m);
        const u64* wq = (const u64*)(Ws + c * SWO + 16 * w);
#pragma unroll
        for (int k = 0; k < 8; k++) {
            u64 wp = wq[k];
#pragma unroll
            for (int m = 0; m < 4; m++)
                acc[k][m] = ffma2(wp, aa[m], acc[k][m]);
        }
    }

    __syncthreads();   // GEMM1 reads done; safe to overwrite Ws and As2

    // stage W2 natural: o<64 -> W2l (p), o>=64 -> W2r (r)
    for (int idx = tid; idx < 64 * 128; idx += 256) {
        int o = idx >> 7, c = idx & 127;
        Ws[c * SWO + o]      = W2l[idx];
        Ws[c * SWO + o + 64] = W2r[idx];
    }
    // epilogue 1: bias + relu -> h duplicated into As2[o][n]
#pragma unroll
    for (int k = 0; k < 8; k++) {
        int o = 16 * w + 2 * k;
        float blo = bs[o], bhi = bs[o + 1];
#pragma unroll
        for (int m = 0; m < 4; m++) {
            int n = ln + 32 * m;
            float lo, hi;
            upk2(acc[k][m], lo, hi);
            lo = fmaxf(lo + blo, 0.f);
            hi = fmaxf(hi + bhi, 0.f);
            As2[o * SAD + n]       = make_float2(lo, lo);
            As2[(o + 1) * SAD + n] = make_float2(hi, hi);
            acc[k][m] = 0ULL;
        }
    }
    __syncthreads();

    // ---- GEMM2 ----
#pragma unroll 2
    for (int c = 0; c < 128; c++) {
        u64 aa[4];
#pragma unroll
        for (int m = 0; m < 4; m++)
            aa[m] = *(const u64*)(As2 + c * SAD + ln + 32 * m);
        const u64* wq = (const u64*)(Ws + c * SWO + 16 * w);
#pragma unroll
        for (int k = 0; k < 8; k++) {
            u64 wp = wq[k];
#pragma unroll
            for (int m = 0; m < 4; m++)
                acc[k][m] = ffma2(wp, aa[m], acc[k][m]);
        }
    }

    // epilogue 2: out-pair is contiguous in memory -> STG.64
    // outs 0..63 -> g_p, 64..127 -> g_r (pairs never straddle: o even)
#pragma unroll
    for (int k = 0; k < 8; k++) {
        int o = 16 * w + 2 * k;
        float* base = (o < 64) ? (g_p + o) : (g_r + (o - 64));
#pragma unroll
        for (int m = 0; m < 4; m++) {
            int n = n0 + ln + 32 * m;
            if (n < NN) {
                float lo, hi;
                upk2(acc[k][m], lo, hi);
                *(float2*)(base + (size_t)n * 64) = make_float2(lo, hi);
            }
        }
    }
}

// ---------------- layer-2 aggregation + epilogue (half-warp per node) --------

__global__ void k_agg_out(const float* __restrict__ b2, float* __restrict__ out) {
    int hw = (blockIdx.x * blockDim.x + threadIdx.x) >> 4;
    int lane = threadIdx.x & 15;
    if (hw >= NN) return;
    int start = g_row_start[hw];
    int d = g_deg[hw];
    const int* cs = g_csr_src + start;
    float4 a[8];
#pragma unroll
    for (int k = 0; k < 8; k++) a[k] = make_float4(0.f, 0.f, 0.f, 0.f);
    int j = 0;
    for (; j + 8 <= d; j += 8) {
        int s[8];
#pragma unroll
        for (int k = 0; k < 8; k++) s[k] = cs[j + k];
#pragma unroll
        for (int k = 0; k < 8; k++) {
            float4 v = ((const float4*)(g_p + (size_t)s[k] * 64))[lane];
            a[k].x += v.x; a[k].y += v.y; a[k].z += v.z; a[k].w += v.w;
        }
    }
    for (; j < d; j++) {
        float4 v = ((const float4*)(g_p + (size_t)cs[j] * 64))[lane];
        a[0].x += v.x; a[0].y += v.y; a[0].z += v.z; a[0].w += v.w;
    }
    float sx = ((a[0].x + a[1].x) + (a[2].x + a[3].x)) + ((a[4].x + a[5].x) + (a[6].x + a[7].x));
    float sy = ((a[0].y + a[1].y) + (a[2].y + a[3].y)) + ((a[4].y + a[5].y) + (a[6].y + a[7].y));
    float sz = ((a[0].z + a[1].z) + (a[2].z + a[3].z)) + ((a[4].z + a[5].z) + (a[6].z + a[7].z));
    float sw = ((a[0].w + a[1].w) + (a[2].w + a[3].w)) + ((a[4].w + a[5].w) + (a[6].w + a[7].w));
    float inv = 1.0f / (float)(d > 0 ? d : 1);
    float4 rr = ((const float4*)(g_r + (size_t)hw * 64))[lane];
    float4 bb = ((const float4*)b2)[lane];
    float vx = sx * inv + bb.x + rr.x;
    float vy = sy * inv + bb.y + rr.y;
    float vz = sz * inv + bb.z + rr.z;
    float vw = sw * inv + bb.w + rr.w;
    float4 o;
    o.x = 1.0f / (1.0f + __expf(-vx));
    o.y = 1.0f / (1.0f + __expf(-vy));
    o.z = 1.0f / (1.0f + __expf(-vz));
    o.w = 1.0f / (1.0f + __expf(-vw));
    ((float4*)(out + (size_t)hw * 64))[lane] = o;
}

// ---------------- launch ----------------

extern "C" void kernel_launch(void* const* d_in, const int* in_sizes, int n_in,
                              void* d_out, int out_size) {
    const float* x   = (const float*)d_in[0];
    const int*   ei  = (const int*)d_in[1];
    const float* W1l = (const float*)d_in[2];
    const float* W1r = (const float*)d_in[3];
    const float* b1  = (const float*)d_in[4];
    const float* W2l = (const float*)d_in[5];
    const float* W2r = (const float*)d_in[6];
    const float* b2  = (const float*)d_in[7];
    float* out = (float*)d_out;

    const int* src = ei;
    const int* dst = ei + EE;

    const int smem = 128 * SWO * (int)sizeof(float)
                   + 128 * SAD * (int)sizeof(float2)
                   + 128 * (int)sizeof(float);               // ~197.5 KB
    cudaFuncSetAttribute(k_xform, cudaFuncAttributeMaxDynamicSharedMemorySize, smem);

    void* degp = 0;
    cudaGetSymbolAddress(&degp, g_deg);
    cudaMemsetAsync(degp, 0, NN * sizeof(int), 0);

    k_count<<<(EE + 255) / 256, 256>>>(dst);
    k_scan<<<1, 1024>>>();
    k_fill<<<(EE + 255) / 256, 256>>>(src, dst);

    k_agg64<<<(NN + 15) / 16, 256>>>(x);
    k_xform<<<(NN + 127) / 128, 256, smem>>>(x, W1l, W1r, b1, W2l, W2r);
    k_agg_out<<<(NN + 15) / 16, 256>>>(b2, out);
}